// round 11
// baseline (speedup 1.0000x reference)
#include <cuda_runtime.h>
#include <cstddef>
#include <cstdint>

// Problem shape (fixed by reference setup_inputs)
#define B_      16
#define T_      2048
#define D_      256
#define K_      8
#define CHUNKS  16                       // blocks per batch
#define TOK_PER_BLK (T_ / CHUNKS)        // 128 tokens per block
#define TILE_T  16
#define NTILES  (TOK_PER_BLK / TILE_T)   // 8 tiles
#define LN_EPS  1e-5f

using ull = unsigned long long;

// Per-(batch,chunk) partial sums: [k][0..255]=sum(w*x), [k][256..511]=sum(w*x^2)
__device__ float g_part[B_][CHUNKS][K_][2 * D_];
__device__ float g_sw[B_][CHUNKS][K_];          // sum of weights per cluster
__device__ unsigned int g_cnt[B_];              // arrival counters (reset each run)

// ---------------------------------------------------------------------------
// f32x2 packed helpers (sm_10x dual fp32 pipe — PTX only)
// ---------------------------------------------------------------------------
__device__ __forceinline__ ull pk2(float lo, float hi) {
    ull r; asm("mov.b64 %0, {%1, %2};" : "=l"(r) : "f"(lo), "f"(hi)); return r;
}
__device__ __forceinline__ float2 unpk(ull v) {
    float2 r; asm("mov.b64 {%0, %1}, %2;" : "=f"(r.x), "=f"(r.y) : "l"(v)); return r;
}
__device__ __forceinline__ ull fma2(ull a, ull b, ull c) {
    ull d; asm("fma.rn.f32x2 %0, %1, %2, %3;" : "=l"(d) : "l"(a), "l"(b), "l"(c)); return d;
}
__device__ __forceinline__ ull mul2(ull a, ull b) {
    ull d; asm("mul.rn.f32x2 %0, %1, %2;" : "=l"(d) : "l"(a), "l"(b)); return d;
}

// ---------------------------------------------------------------------------
// cp.async helpers
// ---------------------------------------------------------------------------
__device__ __forceinline__ void cp_async16(unsigned int saddr, const void* gptr) {
    asm volatile("cp.async.cg.shared.global [%0], [%1], 16;" :: "r"(saddr), "l"(gptr));
}
#define CP_COMMIT() asm volatile("cp.async.commit_group;" ::: "memory")
#define CP_WAIT0()  asm volatile("cp.async.wait_group 0;"  ::: "memory")

// ---------------------------------------------------------------------------
// Main fused kernel: grid (CHUNKS, B_), 256 threads.
// The last-arriving block of each batch also performs the finalize.
// ---------------------------------------------------------------------------
__global__ __launch_bounds__(256, 2)
void ldep_main_kernel(const float* __restrict__ x,
                      const float* __restrict__ centers,
                      const float* __restrict__ scale,
                      const float* __restrict__ temperature,
                      float* __restrict__ out) {
    __shared__ float  xs[2][TILE_T][D_];                // 2 x 16 KB tile buffers
    __shared__ __align__(16) float2 ws2[TILE_T][K_];    // weights duplicated (w,w)
    __shared__ float swred[8][K_];
    __shared__ unsigned int s_old;
    __shared__ float r1[8], r2[8];

    const int b     = blockIdx.y;
    const int chunk = blockIdx.x;
    const int tid   = threadIdx.x;
    const int lane  = tid & 31;
    const int warp  = tid >> 5;

    // Lane's cluster for the weight phase epilogue:
    //   after the pass-based reduce, lane l holds full dots for
    //   g = (l>>3)&3 and g+4; it owns k(l) = g + 4*(l&1).
    const int g   = (lane >> 3) & 3;
    const int kk2 = g + 4 * (lane & 1);

    // ---- Init: centers in packed registers; per-lane selected c2/a ----
    const float tval = __ldg(temperature);
    ull c2r[K_][4];
    float c2n[K_];   // ||c_k||^2 (all lanes)
#pragma unroll
    for (int k = 0; k < K_; k++) {
        const float4* cr = (const float4*)&centers[k * D_];
        float4 ca = __ldg(&cr[lane]);
        float4 cb = __ldg(&cr[lane + 32]);
        c2r[k][0] = pk2(ca.x, ca.y);
        c2r[k][1] = pk2(ca.z, ca.w);
        c2r[k][2] = pk2(cb.x, cb.y);
        c2r[k][3] = pk2(cb.z, cb.w);
        ull n = fma2(c2r[k][0], c2r[k][0],
                fma2(c2r[k][1], c2r[k][1],
                fma2(c2r[k][2], c2r[k][2],
                mul2(c2r[k][3], c2r[k][3]))));
        float2 nn = unpk(n);
        float p = nn.x + nn.y;
#pragma unroll
        for (int o = 16; o > 0; o >>= 1)
            p += __shfl_xor_sync(0xffffffffu, p, o);
        c2n[k] = p;
    }
    float c2sel = c2n[0];
#pragma unroll
    for (int j = 1; j < K_; j++) c2sel = (kk2 == j) ? c2n[j] : c2sel;
    float asel = tval * __ldg(&scale[0]);
#pragma unroll
    for (int j = 1; j < K_; j++) {
        float a = tval * __ldg(&scale[j]);
        asel = (kk2 == j) ? a : asel;
    }

    // ---- Persistent accumulators ----
    // Accumulate phase: thread owns dim pair p = tid&127 -> dims (2p,2p+1),
    // and cluster half h = tid>>7 -> clusters 4h..4h+3.
    const int p = tid & 127;
    const int h = tid >> 7;
    ull acc_wx[4], acc_wx2[4];
#pragma unroll
    for (int j = 0; j < 4; j++) { acc_wx[j] = 0ull; acc_wx2[j] = 0ull; }
    float acc_w = 0.0f;   // at lanes (l&6)==0: partial s_w for cluster kk2

    const float* xb = x + ((size_t)b * T_ + (size_t)chunk * TOK_PER_BLK) * D_;

    // Prefetch tile 0
    {
        const float4* src = (const float4*)xb;
        unsigned int dst = (unsigned int)__cvta_generic_to_shared(&xs[0][0][0]);
#pragma unroll
        for (int i = 0; i < 4; i++)
            cp_async16(dst + (unsigned int)(tid + 256 * i) * 16u, src + tid + 256 * i);
        CP_COMMIT();
    }

    for (int t = 0; t < NTILES; ++t) {
        const int bsel = t & 1;
        CP_WAIT0();
        __syncthreads();

        // Prefetch next tile (overlaps weight+accumulate below)
        if (t + 1 < NTILES) {
            const float4* src = (const float4*)(xb + (size_t)(t + 1) * TILE_T * D_);
            unsigned int dst = (unsigned int)__cvta_generic_to_shared(&xs[(t + 1) & 1][0][0]);
#pragma unroll
            for (int i = 0; i < 4; i++)
                cp_async16(dst + (unsigned int)(tid + 256 * i) * 16u, src + tid + 256 * i);
            CP_COMMIT();
        }

        // ---- Weight phase: warp w handles tokens w, w+8 ----
#pragma unroll
        for (int s = 0; s < 2; ++s) {
            const int tok = warp + 8 * s;
            const float4* xr = (const float4*)&xs[bsel][tok][0];
            float4 a  = xr[lane];
            float4 b4 = xr[lane + 32];
            ull xA0 = pk2(a.x, a.y),   xA1 = pk2(a.z, a.w);
            ull xB0 = pk2(b4.x, b4.y), xB1 = pk2(b4.z, b4.w);

            float red[9];
            {
                ull x2p = fma2(xA0, xA0, fma2(xA1, xA1,
                          fma2(xB0, xB0, mul2(xB1, xB1))));
                float2 u = unpk(x2p);
                red[8] = u.x + u.y;
            }
#pragma unroll
            for (int k = 0; k < K_; k++) {
                ull d = fma2(c2r[k][0], xA0, fma2(c2r[k][1], xA1,
                        fma2(c2r[k][2], xB0, mul2(c2r[k][3], xB1))));
                float2 u = unpk(d);
                red[k] = u.x + u.y;
            }
            // Stage 1: class sums (class = lane mod 8) for all 9 values
#pragma unroll
            for (int j = 0; j < 9; j++)
                red[j] += __shfl_xor_sync(0xffffffffu, red[j], 16);
#pragma unroll
            for (int j = 0; j < 9; j++)
                red[j] += __shfl_xor_sync(0xffffffffu, red[j], 8);

            // Stage 2: three passes over offsets {1,2,4}; the carried value
            // index depends only on lane bits 3-4, so mixing partners
            // (bits 0-2) carry the same value, and the 8 classes sum fully.
            float vA = red[0];                      // will become dot[g]
#pragma unroll
            for (int j = 1; j < 4; j++) vA = (g == j) ? red[j] : vA;
            float vB = red[4];                      // will become dot[g+4]
#pragma unroll
            for (int j = 1; j < 4; j++) vB = (g == j) ? red[4 + j] : vB;
            float vC = red[8];                      // will become x2
#pragma unroll
            for (int o = 1; o <= 4; o <<= 1) {
                vA += __shfl_xor_sync(0xffffffffu, vA, o);
                vB += __shfl_xor_sync(0xffffffffu, vB, o);
                vC += __shfl_xor_sync(0xffffffffu, vC, o);
            }

            // Lane's own logit for cluster kk2 (one exp per lane)
            float dot  = (lane & 1) ? vB : vA;
            float dist = vC - 2.0f * dot + c2sel;
            float lg   = -asel * dist;
            // softmax over the 8 clusters: lanes differing in bits {0,3,4}
            float mx = lg;
            mx = fmaxf(mx, __shfl_xor_sync(0xffffffffu, mx, 1));
            mx = fmaxf(mx, __shfl_xor_sync(0xffffffffu, mx, 8));
            mx = fmaxf(mx, __shfl_xor_sync(0xffffffffu, mx, 16));
            float e = __expf(lg - mx);
            float sm = e;
            sm += __shfl_xor_sync(0xffffffffu, sm, 1);
            sm += __shfl_xor_sync(0xffffffffu, sm, 8);
            sm += __shfl_xor_sync(0xffffffffu, sm, 16);
            float wv = __fdividef(e, sm);
            if ((lane & 6) == 0) {                  // lanes {0,1,8,9,16,17,24,25}
                ws2[tok][kk2] = make_float2(wv, wv);
                acc_w += wv;
            }
        }
        __syncthreads();

        // ---- Accumulate phase (packed f32x2) ----
#pragma unroll 4
        for (int tok = 0; tok < TILE_T; ++tok) {
            ull xv = *(const ull*)&xs[bsel][tok][2 * p];   // dims (2p, 2p+1)
            ull xq = mul2(xv, xv);
            const ulonglong2* wr = (const ulonglong2*)&ws2[tok][4 * h];
            ulonglong2 wA = wr[0];
            ulonglong2 wB = wr[1];
            acc_wx[0]  = fma2(wA.x, xv, acc_wx[0]);
            acc_wx2[0] = fma2(wA.x, xq, acc_wx2[0]);
            acc_wx[1]  = fma2(wA.y, xv, acc_wx[1]);
            acc_wx2[1] = fma2(wA.y, xq, acc_wx2[1]);
            acc_wx[2]  = fma2(wB.x, xv, acc_wx[2]);
            acc_wx2[2] = fma2(wB.x, xq, acc_wx2[2]);
            acc_wx[3]  = fma2(wB.y, xv, acc_wx[3]);
            acc_wx2[3] = fma2(wB.y, xq, acc_wx2[3]);
        }
    }

    // ---- Flush per-block partials (disjoint slots, no atomics) ----
#pragma unroll
    for (int j = 0; j < 4; j++) {
        const int k = 4 * h + j;
        float* base = &g_part[b][chunk][k][0];
        float2 vx = unpk(acc_wx[j]);
        float2 vq = unpk(acc_wx2[j]);
        *(float2*)(base + 2 * p)      = vx;
        *(float2*)(base + D_ + 2 * p) = vq;
    }
    if ((lane & 6) == 0) swred[warp][kk2] = acc_w;
    __syncthreads();
    if (tid < K_) {
        float s = 0.0f;
#pragma unroll
        for (int w = 0; w < 8; w++) s += swred[w][tid];
        g_sw[b][chunk][tid] = s;
    }

    // ---- Last block of this batch performs the finalize ----
    __threadfence();
    if (tid == 0) s_old = atomicAdd(&g_cnt[b], 1u);
    __syncthreads();
    if (s_old != CHUNKS - 1) return;
    __threadfence();   // acquire: order following loads after the arrivals

    const int lane2 = tid & 31, warp2 = tid >> 5;
    for (int k = 0; k < K_; k++) {
        __syncthreads();    // protect r1/r2 reuse across k iterations

        float sw = 0.0f, swx = 0.0f, swx2 = 0.0f;
#pragma unroll
        for (int c = 0; c < CHUNKS; c++) {
            sw   += g_sw[b][c][k];
            swx  += g_part[b][c][k][tid];
            swx2 += g_part[b][c][k][D_ + tid];
        }
        float cc = __ldg(&centers[k * D_ + tid]);

        // Same algebraic decomposition as the reference
        float mean = swx - cc * sw;
        float E    = swx2 - 2.0f * cc * swx + cc * cc * sw;
        float var  = E - mean * mean;

        // LayerNorm stats over the 512 concatenated [mean | var] values
        float s1 = mean + var;
        float s2 = mean * mean + var * var;
#pragma unroll
        for (int o = 16; o > 0; o >>= 1) {
            s1 += __shfl_xor_sync(0xffffffffu, s1, o);
            s2 += __shfl_xor_sync(0xffffffffu, s2, o);
        }
        if (lane2 == 0) { r1[warp2] = s1; r2[warp2] = s2; }
        __syncthreads();
        float S1 = 0.0f, S2 = 0.0f;
#pragma unroll
        for (int i = 0; i < 8; i++) { S1 += r1[i]; S2 += r2[i]; }

        const float mu  = S1 * (1.0f / 512.0f);
        const float v   = S2 * (1.0f / 512.0f) - mu * mu;
        const float inv = rsqrtf(v + LN_EPS);

        float* o = out + ((size_t)b * K_ + k) * (2 * D_);
        o[tid]      = (mean - mu) * inv;
        o[D_ + tid] = (var  - mu) * inv;
    }
    if (tid == 0) g_cnt[b] = 0;   // reset for the next (graph-replayed) run
}

// ---------------------------------------------------------------------------
// Launch: inputs per metadata order: x, centers, scale, temperature
// ---------------------------------------------------------------------------
extern "C" void kernel_launch(void* const* d_in, const int* in_sizes, int n_in,
                              void* d_out, int out_size) {
    const float* x           = (const float*)d_in[0];
    const float* centers     = (const float*)d_in[1];
    const float* scale       = (const float*)d_in[2];
    const float* temperature = (const float*)d_in[3];
    float* out               = (float*)d_out;

    ldep_main_kernel<<<dim3(CHUNKS, B_), 256>>>(x, centers, scale, temperature, out);
}